// round 1
// baseline (speedup 1.0000x reference)
#include <cuda_runtime.h>
#include <cstdint>

// Problem constants
#define T_TOK 4096        // B*S tokens
#define H_DIM 1024
#define F_DIM 4096
#define N_EXP 8

// -------- device scratch (no allocations allowed; globals are the sanctioned path) -----
__device__ int   g_cnt[N_EXP];
__device__ int   g_list[N_EXP][T_TOK];
__device__ float g_wt[N_EXP][T_TOK];
__device__ float g_h[(size_t)N_EXP * T_TOK * F_DIM];   // GELU(X@W1+b1) per expert-row

// -------------------------------- helpers ---------------------------------
__device__ __forceinline__ float to_tf32(float x) {
    asm("cvt.rna.tf32.f32 %0, %1;" : "=f"(x) : "f"(x));
    return x;
}

__device__ __forceinline__ void mma_tf32(float c[4],
                                         uint32_t a0, uint32_t a1, uint32_t a2, uint32_t a3,
                                         uint32_t b0, uint32_t b1) {
    asm volatile(
        "mma.sync.aligned.m16n8k8.row.col.f32.tf32.tf32.f32 "
        "{%0,%1,%2,%3}, {%4,%5,%6,%7}, {%8,%9}, {%0,%1,%2,%3};"
        : "+f"(c[0]), "+f"(c[1]), "+f"(c[2]), "+f"(c[3])
        : "r"(a0), "r"(a1), "r"(a2), "r"(a3), "r"(b0), "r"(b1));
}

__device__ __forceinline__ float gelu_exact(float x) {
    return 0.5f * x * (1.0f + erff(x * 0.70710678118654752f));
}

// ------------------------------ zero kernel --------------------------------
__global__ void zero_kernel(float* __restrict__ out) {
    int i = blockIdx.x * blockDim.x + threadIdx.x;
    if (i < T_TOK * H_DIM) out[i] = 0.0f;
    if (i < N_EXP) g_cnt[i] = 0;
}

// ------------------------------ router kernel ------------------------------
// One warp per token: 8 logits over H=1024, top-2, renormalized softmax weights.
__global__ void router_kernel(const float* __restrict__ x,
                              const float* __restrict__ rw,
                              const float* __restrict__ rb) {
    int gwarp = (blockIdx.x * blockDim.x + threadIdx.x) >> 5;
    if (gwarp >= T_TOK) return;
    int lane = threadIdx.x & 31;
    const float* xr = x + (size_t)gwarp * H_DIM;

    float p[N_EXP];
#pragma unroll
    for (int e = 0; e < N_EXP; e++) p[e] = 0.0f;

    for (int i = lane; i < H_DIM; i += 32) {
        float xv = xr[i];
        const float4* r4 = (const float4*)(rw + i * N_EXP);
        float4 ra = r4[0];
        float4 rc = r4[1];
        p[0] += xv * ra.x; p[1] += xv * ra.y; p[2] += xv * ra.z; p[3] += xv * ra.w;
        p[4] += xv * rc.x; p[5] += xv * rc.y; p[6] += xv * rc.z; p[7] += xv * rc.w;
    }
#pragma unroll
    for (int e = 0; e < N_EXP; e++) {
#pragma unroll
        for (int o = 16; o > 0; o >>= 1) p[e] += __shfl_xor_sync(0xffffffffu, p[e], o);
    }
    if (lane == 0) {
#pragma unroll
        for (int e = 0; e < N_EXP; e++) p[e] += rb[e];
        // top-2 (ties -> lowest index, matching lax.top_k)
        int i1 = 0;
#pragma unroll
        for (int e = 1; e < N_EXP; e++) if (p[e] > p[i1]) i1 = e;
        int i2 = (i1 == 0) ? 1 : 0;
#pragma unroll
        for (int e = 0; e < N_EXP; e++) if (e != i1 && p[e] > p[i2]) i2 = e;
        // renormalized top-2 softmax weights
        float wa = 1.0f / (1.0f + expf(p[i2] - p[i1]));
        float wb = 1.0f - wa;
        int p1 = atomicAdd(&g_cnt[i1], 1);
        g_list[i1][p1] = gwarp; g_wt[i1][p1] = wa;
        int p2 = atomicAdd(&g_cnt[i2], 1);
        g_list[i2][p2] = gwarp; g_wt[i2][p2] = wb;
    }
}

// --------------------------- grouped GEMM kernel ---------------------------
// PHASE 1: A = gathered X rows (K=H), B = w1[e] (HxF), epilogue GELU -> g_h
// PHASE 2: A = g_h rows      (K=F), B = w2[e] (FxH), epilogue weighted atomicAdd -> out
// Tile: 128x128x32, 256 threads (8 warps as 2m x 4n, warp tile 64x32), tf32 mma.
#define BK 32
#define SROW 36   // padded smem row stride (floats) -> conflict-free frag loads

template <int KDIM, int NDIM, int PHASE>
__global__ void __launch_bounds__(256)
gemm_expert_kernel(const float* __restrict__ Abase,
                   const float* __restrict__ W,
                   const float* __restrict__ bias,
                   float* __restrict__ out) {
    __shared__ float sA[128 * SROW];
    __shared__ float sB[128 * SROW];
    __shared__ int   sTok[128];
    __shared__ float sWt[128];

    const int e   = blockIdx.z;
    const int cnt = g_cnt[e];
    const int m0  = blockIdx.x * 128;
    if (m0 >= cnt) return;
    const int n0  = blockIdx.y * 128;
    const int tid = threadIdx.x;
    const int lane = tid & 31;
    const int warp = tid >> 5;
    const int wm = (warp & 1) * 64;   // warp m-offset within tile
    const int wn = (warp >> 1) * 32;  // warp n-offset within tile
    const int grp = lane >> 2;        // 0..7
    const int tig = lane & 3;         // 0..3

    if (tid < 128) {
        int mc = min(m0 + tid, cnt - 1);
        sTok[tid] = g_list[e][mc];
        sWt[tid]  = g_wt[e][mc];
    }
    __syncthreads();

    const float* Aexp = (PHASE == 1) ? Abase : (g_h + (size_t)e * T_TOK * F_DIM);
    const float* Wexp = W + (size_t)e * KDIM * NDIM;

    float acc[4][4][4];
#pragma unroll
    for (int mi = 0; mi < 4; mi++)
#pragma unroll
        for (int ni = 0; ni < 4; ni++)
#pragma unroll
            for (int c = 0; c < 4; c++) acc[mi][ni][c] = 0.0f;

    for (int k0 = 0; k0 < KDIM; k0 += BK) {
        // ---- load A tile: 128 rows x 32 floats (as float4), convert to tf32 ----
#pragma unroll
        for (int i = 0; i < 4; i++) {
            int idx = tid + i * 256;
            int r = idx >> 3;
            int c4 = (idx & 7) * 4;
            const float* src;
            if (PHASE == 1) {
                src = Aexp + (size_t)sTok[r] * H_DIM + k0 + c4;
            } else {
                int rr = min(m0 + r, cnt - 1);
                src = Aexp + (size_t)rr * F_DIM + k0 + c4;
            }
            float4 v = *(const float4*)src;
            float* d = &sA[r * SROW + c4];
            d[0] = to_tf32(v.x); d[1] = to_tf32(v.y);
            d[2] = to_tf32(v.z); d[3] = to_tf32(v.w);
        }
        // ---- load B tile: 32 k-rows x 128 n, store transposed sB[n][k] ----
#pragma unroll
        for (int i = 0; i < 4; i++) {
            int idx = tid + i * 256;
            int kk = idx >> 5;
            int c4 = (idx & 31) * 4;
            float4 v = *(const float4*)(Wexp + (size_t)(k0 + kk) * NDIM + n0 + c4);
            sB[(c4 + 0) * SROW + kk] = to_tf32(v.x);
            sB[(c4 + 1) * SROW + kk] = to_tf32(v.y);
            sB[(c4 + 2) * SROW + kk] = to_tf32(v.z);
            sB[(c4 + 3) * SROW + kk] = to_tf32(v.w);
        }
        __syncthreads();

        // ---- compute: 4 k-steps of m16n8k8 ----
#pragma unroll
        for (int ks = 0; ks < 4; ks++) {
            int kb = ks * 8;
            uint32_t bfr[4][2];
#pragma unroll
            for (int ni = 0; ni < 4; ni++) {
                int n = wn + ni * 8 + grp;
                bfr[ni][0] = __float_as_uint(sB[n * SROW + kb + tig]);
                bfr[ni][1] = __float_as_uint(sB[n * SROW + kb + tig + 4]);
            }
#pragma unroll
            for (int mi = 0; mi < 4; mi++) {
                int m = wm + mi * 16;
                uint32_t a0 = __float_as_uint(sA[(m + grp) * SROW + kb + tig]);
                uint32_t a1 = __float_as_uint(sA[(m + grp + 8) * SROW + kb + tig]);
                uint32_t a2 = __float_as_uint(sA[(m + grp) * SROW + kb + tig + 4]);
                uint32_t a3 = __float_as_uint(sA[(m + grp + 8) * SROW + kb + tig + 4]);
#pragma unroll
                for (int ni = 0; ni < 4; ni++)
                    mma_tf32(acc[mi][ni], a0, a1, a2, a3, bfr[ni][0], bfr[ni][1]);
            }
        }
        __syncthreads();
    }

    // ------------------------------ epilogue ------------------------------
#pragma unroll
    for (int mi = 0; mi < 4; mi++) {
#pragma unroll
        for (int ni = 0; ni < 4; ni++) {
            int gn = n0 + wn + ni * 8 + tig * 2;
            float bv0 = bias[(size_t)e * NDIM + gn];
            float bv1 = bias[(size_t)e * NDIM + gn + 1];
#pragma unroll
            for (int half = 0; half < 2; half++) {
                int r = m0 + wm + mi * 16 + grp + half * 8;  // global row within expert
                if (r < cnt) {
                    float v0 = acc[mi][ni][half * 2 + 0] + bv0;
                    float v1 = acc[mi][ni][half * 2 + 1] + bv1;
                    if (PHASE == 1) {
                        float* dst = g_h + (size_t)e * T_TOK * F_DIM + (size_t)r * F_DIM + gn;
                        dst[0] = gelu_exact(v0);
                        dst[1] = gelu_exact(v1);
                    } else {
                        int   tok = sTok[r - m0];
                        float wt  = sWt[r - m0];
                        atomicAdd(&out[(size_t)tok * H_DIM + gn],     wt * v0);
                        atomicAdd(&out[(size_t)tok * H_DIM + gn + 1], wt * v1);
                    }
                }
            }
        }
    }
}

// ------------------------------ launch ------------------------------------
extern "C" void kernel_launch(void* const* d_in, const int* in_sizes, int n_in,
                              void* d_out, int out_size) {
    const float* x   = (const float*)d_in[0];  // [B,S,H] = [4096,1024]
    const float* rw  = (const float*)d_in[1];  // [H,E]
    const float* rb  = (const float*)d_in[2];  // [E]
    const float* w1  = (const float*)d_in[3];  // [E,H,F]
    const float* b1  = (const float*)d_in[4];  // [E,F]
    const float* w2  = (const float*)d_in[5];  // [E,F,H]
    const float* b2  = (const float*)d_in[6];  // [E,H]
    float* out = (float*)d_out;                // [4096,1024] fp32

    zero_kernel<<<(T_TOK * H_DIM + 255) / 256, 256>>>(out);
    router_kernel<<<(T_TOK * 32 + 255) / 256, 256>>>(x, rw, rb);
    // GEMM1: M<=4096/expert, N=F=4096, K=H=1024
    gemm_expert_kernel<H_DIM, F_DIM, 1>
        <<<dim3(T_TOK / 128, F_DIM / 128, N_EXP), 256>>>(x, w1, b1, nullptr);
    // GEMM2: M<=4096/expert, N=H=1024, K=F=4096
    gemm_expert_kernel<F_DIM, H_DIM, 2>
        <<<dim3(T_TOK / 128, H_DIM / 128, N_EXP), 256>>>(nullptr, w2, b2, out);
}

// round 3
// speedup vs baseline: 1.2673x; 1.2673x over previous
#include <cuda_runtime.h>
#include <cstdint>

// Problem constants
#define T_TOK 4096
#define H_DIM 1024
#define F_DIM 4096
#define N_EXP 8

// Tiling: CTA 128m x 256n x 32k, 8 warps (2m x 4n), warp tile 64x64
#define NT 256
#define KC 32
#define A_STAGE_BYTES (128 * 128)             // 128 rows x 128B
#define B_STAGE_BYTES (NT * 128)              // 256 rows x 128B
#define STAGE_STRIDE  (A_STAGE_BYTES + B_STAGE_BYTES)
#define SMEM_TILES_OFF 1024
#define SMEM_BYTES (SMEM_TILES_OFF + 2 * STAGE_STRIDE)   // 99328

// -------- device scratch --------
__device__ int   g_cnt[N_EXP];
__device__ int   g_list[N_EXP][T_TOK];
__device__ float g_wt[N_EXP][T_TOK];
__device__ float g_h[(size_t)N_EXP * T_TOK * F_DIM];

// -------- helpers --------
__device__ __forceinline__ float to_tf32(float x) {
    asm("cvt.rna.tf32.f32 %0, %1;" : "=f"(x) : "f"(x));
    return x;
}
__device__ __forceinline__ void mma_tf32(float c[4],
                                         uint32_t a0, uint32_t a1, uint32_t a2, uint32_t a3,
                                         uint32_t b0, uint32_t b1) {
    asm volatile(
        "mma.sync.aligned.m16n8k8.row.col.f32.tf32.tf32.f32 "
        "{%0,%1,%2,%3}, {%4,%5,%6,%7}, {%8,%9}, {%0,%1,%2,%3};"
        : "+f"(c[0]), "+f"(c[1]), "+f"(c[2]), "+f"(c[3])
        : "r"(a0), "r"(a1), "r"(a2), "r"(a3), "r"(b0), "r"(b1));
}
__device__ __forceinline__ float gelu_exact(float x) {
    return 0.5f * x * (1.0f + erff(x * 0.70710678118654752f));
}
#define SWZ(x) ((x) ^ (((x) >> 3) & 0x70))

// ------------------------------ zero kernel --------------------------------
__global__ void zero_kernel(float* __restrict__ out) {
    int i = blockIdx.x * blockDim.x + threadIdx.x;
    if (i < T_TOK * H_DIM) out[i] = 0.0f;
    if (i < N_EXP) g_cnt[i] = 0;
}

// ------------------------------ router kernel ------------------------------
__global__ void router_kernel(const float* __restrict__ x,
                              const float* __restrict__ rw,
                              const float* __restrict__ rb) {
    int gwarp = (blockIdx.x * blockDim.x + threadIdx.x) >> 5;
    if (gwarp >= T_TOK) return;
    int lane = threadIdx.x & 31;
    const float* xr = x + (size_t)gwarp * H_DIM;
    float p[N_EXP];
#pragma unroll
    for (int e = 0; e < N_EXP; e++) p[e] = 0.0f;
    for (int i = lane; i < H_DIM; i += 32) {
        float xv = xr[i];
        const float4* r4 = (const float4*)(rw + i * N_EXP);
        float4 ra = r4[0], rc = r4[1];
        p[0] += xv * ra.x; p[1] += xv * ra.y; p[2] += xv * ra.z; p[3] += xv * ra.w;
        p[4] += xv * rc.x; p[5] += xv * rc.y; p[6] += xv * rc.z; p[7] += xv * rc.w;
    }
#pragma unroll
    for (int e = 0; e < N_EXP; e++) {
#pragma unroll
        for (int o = 16; o > 0; o >>= 1) p[e] += __shfl_xor_sync(0xffffffffu, p[e], o);
    }
    if (lane == 0) {
#pragma unroll
        for (int e = 0; e < N_EXP; e++) p[e] += rb[e];
        int i1 = 0;
#pragma unroll
        for (int e = 1; e < N_EXP; e++) if (p[e] > p[i1]) i1 = e;
        int i2 = (i1 == 0) ? 1 : 0;
#pragma unroll
        for (int e = 0; e < N_EXP; e++) if (e != i1 && p[e] > p[i2]) i2 = e;
        float wa = 1.0f / (1.0f + expf(p[i2] - p[i1]));
        float wb = 1.0f - wa;
        int p1 = atomicAdd(&g_cnt[i1], 1);
        g_list[i1][p1] = gwarp; g_wt[i1][p1] = wa;
        int p2 = atomicAdd(&g_cnt[i2], 1);
        g_list[i2][p2] = gwarp; g_wt[i2][p2] = wb;
    }
}

// --------------------------- grouped GEMM kernel ---------------------------
// PHASE 1: A = gathered X rows (K=H), W = w1[e] (HxF), epilogue GELU -> g_h
// PHASE 2: A = g_h rows      (K=F), W = w2[e] (FxH), weighted atomicAdd -> out
template <int KDIM, int NDIM, int PHASE>
__global__ void __launch_bounds__(256)
moe_gemm(const float* __restrict__ Abase,
         const float* __restrict__ W,
         const float* __restrict__ bias,
         float* __restrict__ out) {
    extern __shared__ char smem[];
    const int e   = blockIdx.z;
    const int cnt = g_cnt[e];
    const int m0  = blockIdx.x * 128;
    if (m0 >= cnt) return;
    const int n0  = blockIdx.y * NT;

    const int tid  = threadIdx.x;
    const int lane = tid & 31;
    const int warp = tid >> 5;
    const int wm   = (warp & 1) * 64;
    const int wn   = (warp >> 1) * 64;
    const int grp  = lane >> 2;
    const int tig  = lane & 3;

    int*   sTok = (int*)(smem);          // [128]
    float* sWt  = (float*)(smem + 512);  // [128]

    if (tid < 128) {
        int mc = min(m0 + tid, cnt - 1);
        sTok[tid] = g_list[e][mc];
        sWt[tid]  = g_wt[e][mc];
    }
    __syncthreads();

    const float* Aexp = (PHASE == 1) ? Abase : (g_h + (size_t)e * T_TOK * F_DIM);
    const float* Wexp = W + (size_t)e * KDIM * NDIM;
    constexpr int NC = KDIM / KC;

    // ---- staging registers ----
    float4 aReg[4];       // A: 128x32 / 256 thr = 4 float4
    float  bReg[8][4];    // B: 256x32 / 256 thr = 8 groups of 4 k-strided scalars

    // per-thread A-loader coords
    const int aR  = tid >> 3;          // row 0..127 (x2 over 512.. no: 4 iters below)
    // (computed per-iter below)

    auto ldgA = [&](int c) {
#pragma unroll
        for (int i = 0; i < 4; i++) {
            int idx = tid + i * 256;
            int r   = idx >> 3;
            int c4  = (idx & 7) * 4;
            const float* src;
            if (PHASE == 1) src = Abase + (size_t)sTok[r] * KDIM + c * KC + c4;
            else            src = Aexp + (size_t)min(m0 + r, cnt - 1) * KDIM + c * KC + c4;
            aReg[i] = *(const float4*)src;
        }
    };
    auto ldgB = [&](int c) {
#pragma unroll
        for (int i = 0; i < 8; i++) {
            int idx = tid + i * 256;
            int n   = idx & (NT - 1);
            int k4  = (idx >> 8) * 4;
            const float* src = Wexp + (size_t)(c * KC + k4) * NDIM + n0 + n;
            bReg[i][0] = src[0];
            bReg[i][1] = src[NDIM];
            bReg[i][2] = src[2 * NDIM];
            bReg[i][3] = src[3 * NDIM];
        }
    };
    auto stsAB = [&](int s) {
        char* aB = smem + SMEM_TILES_OFF + s * STAGE_STRIDE;
        char* bB = aB + A_STAGE_BYTES;
#pragma unroll
        for (int i = 0; i < 4; i++) {
            int idx = tid + i * 256;
            int r   = idx >> 3;
            int c4  = (idx & 7) * 4;
            float4 v = aReg[i];
            float* d = (float*)(aB + SWZ((uint32_t)(r * 128 + c4 * 4)));
            d[0] = to_tf32(v.x); d[1] = to_tf32(v.y);
            d[2] = to_tf32(v.z); d[3] = to_tf32(v.w);
        }
#pragma unroll
        for (int i = 0; i < 8; i++) {
            int idx = tid + i * 256;
            int n   = idx & (NT - 1);
            int k4  = (idx >> 8) * 4;
            float* d = (float*)(bB + SWZ((uint32_t)(n * 128 + k4 * 4)));
            d[0] = to_tf32(bReg[i][0]); d[1] = to_tf32(bReg[i][1]);
            d[2] = to_tf32(bReg[i][2]); d[3] = to_tf32(bReg[i][3]);
        }
    };

    float acc[4][8][4];
#pragma unroll
    for (int mi = 0; mi < 4; mi++)
#pragma unroll
        for (int ni = 0; ni < 8; ni++)
#pragma unroll
            for (int q = 0; q < 4; q++) acc[mi][ni][q] = 0.0f;

    // ---- prologue ----
    ldgA(0); ldgB(0);
    stsAB(0);
    ldgA(1); ldgB(1);
    __syncthreads();

    // ---- mainloop: MMA(c) -> STS(c+1) -> LDG(c+2) -> sync ----
#pragma unroll 2
    for (int c = 0; c < NC; c++) {
        const char* aB = smem + SMEM_TILES_OFF + (c & 1) * STAGE_STRIDE;
        const char* bB = aB + A_STAGE_BYTES;
#pragma unroll
        for (int ks = 0; ks < 4; ks++) {
            const int kb = ks * 8;
            uint32_t b0[8], b1[8];
#pragma unroll
            for (int ni = 0; ni < 8; ni++) {
                int n = wn + ni * 8 + grp;
                b0[ni] = *(const uint32_t*)(bB + SWZ((uint32_t)(n * 128 + (kb + tig) * 4)));
                b1[ni] = *(const uint32_t*)(bB + SWZ((uint32_t)(n * 128 + (kb + tig + 4) * 4)));
            }
#pragma unroll
            for (int mi = 0; mi < 4; mi++) {
                int m = wm + mi * 16;
                uint32_t a0 = *(const uint32_t*)(aB + SWZ((uint32_t)((m + grp) * 128 + (kb + tig) * 4)));
                uint32_t a1 = *(const uint32_t*)(aB + SWZ((uint32_t)((m + grp + 8) * 128 + (kb + tig) * 4)));
                uint32_t a2 = *(const uint32_t*)(aB + SWZ((uint32_t)((m + grp) * 128 + (kb + tig + 4) * 4)));
                uint32_t a3 = *(const uint32_t*)(aB + SWZ((uint32_t)((m + grp + 8) * 128 + (kb + tig + 4) * 4)));
#pragma unroll
                for (int ni = 0; ni < 8; ni++)
                    mma_tf32(acc[mi][ni], a0, a1, a2, a3, b0[ni], b1[ni]);
            }
        }
        if (c + 1 < NC) stsAB((c + 1) & 1);
        if (c + 2 < NC) { ldgA(c + 2); ldgB(c + 2); }
        __syncthreads();
    }

    // ------------------------------ epilogue ------------------------------
#pragma unroll
    for (int mi = 0; mi < 4; mi++) {
#pragma unroll
        for (int ni = 0; ni < 8; ni++) {
            int gn = n0 + wn + ni * 8 + tig * 2;
            float bv0 = bias[(size_t)e * NDIM + gn];
            float bv1 = bias[(size_t)e * NDIM + gn + 1];
#pragma unroll
            for (int half = 0; half < 2; half++) {
                int r = m0 + wm + mi * 16 + grp + half * 8;
                if (r < cnt) {
                    float v0 = acc[mi][ni][half * 2 + 0] + bv0;
                    float v1 = acc[mi][ni][half * 2 + 1] + bv1;
                    if (PHASE == 1) {
                        float* dst = g_h + (size_t)e * T_TOK * F_DIM + (size_t)r * F_DIM + gn;
                        dst[0] = gelu_exact(v0);
                        dst[1] = gelu_exact(v1);
                    } else {
                        int   tok = sTok[r - m0];
                        float wt  = sWt[r - m0];
                        atomicAdd(&out[(size_t)tok * H_DIM + gn],     wt * v0);
                        atomicAdd(&out[(size_t)tok * H_DIM + gn + 1], wt * v1);
                    }
                }
            }
        }
    }
}

// ------------------------------ launch ------------------------------------
extern "C" void kernel_launch(void* const* d_in, const int* in_sizes, int n_in,
                              void* d_out, int out_size) {
    const float* x  = (const float*)d_in[0];
    const float* rw = (const float*)d_in[1];
    const float* rb = (const float*)d_in[2];
    const float* w1 = (const float*)d_in[3];
    const float* b1 = (const float*)d_in[4];
    const float* w2 = (const float*)d_in[5];
    const float* b2 = (const float*)d_in[6];
    float* out = (float*)d_out;

    cudaFuncSetAttribute(moe_gemm<H_DIM, F_DIM, 1>,
                         cudaFuncAttributeMaxDynamicSharedMemorySize, SMEM_BYTES);
    cudaFuncSetAttribute(moe_gemm<F_DIM, H_DIM, 2>,
                         cudaFuncAttributeMaxDynamicSharedMemorySize, SMEM_BYTES);

    zero_kernel<<<(T_TOK * H_DIM + 255) / 256, 256>>>(out);
    router_kernel<<<(T_TOK * 32 + 255) / 256, 256>>>(x, rw, rb);
    moe_gemm<H_DIM, F_DIM, 1>
        <<<dim3(T_TOK / 128, F_DIM / NT, N_EXP), 256, SMEM_BYTES>>>(x, w1, b1, nullptr);
    moe_gemm<F_DIM, H_DIM, 2>
        <<<dim3(T_TOK / 128, H_DIM / NT, N_EXP), 256, SMEM_BYTES>>>(nullptr, w2, b2, out);
}

// round 5
// speedup vs baseline: 2.0757x; 1.6379x over previous
#include <cuda_runtime.h>
#include <cstdint>

// Problem constants
#define T_TOK 4096
#define H_DIM 1024
#define F_DIM 4096
#define N_EXP 8

// Tiling: CTA 128m x 256n x 32k, 8 warps (2m x 4n), warp tile 64x64, 3-stage cp.async
#define NT 256
#define KC 32
#define NSTAGE 3
#define A_STAGE_BYTES (128 * 128)             // 128 rows x 128B
#define B_STAGE_BYTES (KC * NT * 4)           // 32 k-rows x 1KB
#define STAGE_STRIDE  (A_STAGE_BYTES + B_STAGE_BYTES)   // 48KB
#define SMEM_TILES_OFF 1024
#define SMEM_BYTES (SMEM_TILES_OFF + NSTAGE * STAGE_STRIDE)

// -------- device scratch --------
__device__ int   g_cnt[N_EXP];
__device__ int   g_list[N_EXP][T_TOK];
__device__ float g_wt[N_EXP][T_TOK];
__device__ float g_h[(size_t)N_EXP * T_TOK * F_DIM];

// -------- helpers --------
__device__ __forceinline__ float to_tf32(float x) {
    asm("cvt.rna.tf32.f32 %0, %1;" : "=f"(x) : "f"(x));
    return x;
}
__device__ __forceinline__ uint32_t cvt_frag(uint32_t u) {
    float f = __uint_as_float(u);
    asm("cvt.rna.tf32.f32 %0, %0;" : "+f"(f));
    return __float_as_uint(f);
}
__device__ __forceinline__ void mma_tf32(float c[4],
                                         uint32_t a0, uint32_t a1, uint32_t a2, uint32_t a3,
                                         uint32_t b0, uint32_t b1) {
    asm volatile(
        "mma.sync.aligned.m16n8k8.row.col.f32.tf32.tf32.f32 "
        "{%0,%1,%2,%3}, {%4,%5,%6,%7}, {%8,%9}, {%0,%1,%2,%3};"
        : "+f"(c[0]), "+f"(c[1]), "+f"(c[2]), "+f"(c[3])
        : "r"(a0), "r"(a1), "r"(a2), "r"(a3), "r"(b0), "r"(b1));
}
__device__ __forceinline__ float gelu_exact(float x) {
    return 0.5f * x * (1.0f + erff(x * 0.70710678118654752f));
}
__device__ __forceinline__ uint32_t smem_u32(const void* p) {
    uint32_t a;
    asm("{ .reg .u64 t; cvta.to.shared.u64 t, %1; cvt.u32.u64 %0, t; }" : "=r"(a) : "l"(p));
    return a;
}
__device__ __forceinline__ void cp16(uint32_t dst, const void* src) {
    asm volatile("cp.async.cg.shared.global [%0], [%1], 16;" :: "r"(dst), "l"(src) : "memory");
}
#define CP_COMMIT() asm volatile("cp.async.commit_group;" ::: "memory")
#define CP_WAIT1()  asm volatile("cp.async.wait_group 1;" ::: "memory")
#define SWZ(x) ((x) ^ (((x) >> 3) & 0x70))

// ------------------------------ zero kernel --------------------------------
__global__ void zero_kernel(float* __restrict__ out) {
    int i = blockIdx.x * blockDim.x + threadIdx.x;
    if (i < T_TOK * H_DIM) out[i] = 0.0f;
    if (i < N_EXP) g_cnt[i] = 0;
}

// ------------------------------ router kernel ------------------------------
__global__ void router_kernel(const float* __restrict__ x,
                              const float* __restrict__ rw,
                              const float* __restrict__ rb) {
    int gwarp = (blockIdx.x * blockDim.x + threadIdx.x) >> 5;
    if (gwarp >= T_TOK) return;
    int lane = threadIdx.x & 31;
    const float* xr = x + (size_t)gwarp * H_DIM;
    float p[N_EXP];
#pragma unroll
    for (int e = 0; e < N_EXP; e++) p[e] = 0.0f;
    for (int i = lane; i < H_DIM; i += 32) {
        float xv = xr[i];
        const float4* r4 = (const float4*)(rw + i * N_EXP);
        float4 ra = r4[0], rc = r4[1];
        p[0] += xv * ra.x; p[1] += xv * ra.y; p[2] += xv * ra.z; p[3] += xv * ra.w;
        p[4] += xv * rc.x; p[5] += xv * rc.y; p[6] += xv * rc.z; p[7] += xv * rc.w;
    }
#pragma unroll
    for (int e = 0; e < N_EXP; e++) {
#pragma unroll
        for (int o = 16; o > 0; o >>= 1) p[e] += __shfl_xor_sync(0xffffffffu, p[e], o);
    }
    if (lane == 0) {
#pragma unroll
        for (int e = 0; e < N_EXP; e++) p[e] += rb[e];
        int i1 = 0;
#pragma unroll
        for (int e = 1; e < N_EXP; e++) if (p[e] > p[i1]) i1 = e;
        int i2 = (i1 == 0) ? 1 : 0;
#pragma unroll
        for (int e = 0; e < N_EXP; e++) if (e != i1 && p[e] > p[i2]) i2 = e;
        float wa = 1.0f / (1.0f + expf(p[i2] - p[i1]));
        float wb = 1.0f - wa;
        int p1 = atomicAdd(&g_cnt[i1], 1);
        g_list[i1][p1] = gwarp; g_wt[i1][p1] = wa;
        int p2 = atomicAdd(&g_cnt[i2], 1);
        g_list[i2][p2] = gwarp; g_wt[i2][p2] = wb;
    }
}

// --------------------------- grouped GEMM kernel ---------------------------
// A smem: [m(128)][k(32)] SW128 rows of 128B.   B smem: [k(32)][n(256)] with
// n ^= (k&3)<<3 swizzle (conflict-free frags, 16B-contiguous for cp.async).
template <int KDIM, int NDIM, int PHASE>
__global__ void __launch_bounds__(256)
moe_gemm(const float* __restrict__ Abase,
         const float* __restrict__ W,
         const float* __restrict__ bias,
         float* __restrict__ out) {
    extern __shared__ char smem[];
    const int e   = blockIdx.z;
    const int cnt = g_cnt[e];
    const int m0  = blockIdx.x * 128;
    if (m0 >= cnt) return;
    const int n0  = blockIdx.y * NT;

    const int tid  = threadIdx.x;
    const int lane = tid & 31;
    const int warp = tid >> 5;
    const int wm   = (warp & 1) * 64;
    const int wn   = (warp >> 1) * 64;
    const int grp  = lane >> 2;
    const int tig  = lane & 3;

    int*   sTok = (int*)(smem);          // [128]
    float* sWt  = (float*)(smem + 512);  // [128]

    if (tid < 128) {
        int mc = min(m0 + tid, cnt - 1);
        sTok[tid] = g_list[e][mc];
        sWt[tid]  = g_wt[e][mc];
    }
    __syncthreads();

    const float* Aexp = (PHASE == 1) ? Abase : (g_h + (size_t)e * T_TOK * F_DIM);
    const float* Wexp = W + (size_t)e * KDIM * NDIM;
    constexpr int NC = KDIM / KC;
    const uint32_t sb = smem_u32(smem) + SMEM_TILES_OFF;

    // per-thread loader coords (fixed)
    const int aRow = tid >> 1;                 // 0..127 (2 thr/row, 2 iters -> 4 chunks/row)
    const int aC4  = (tid & 1) * 4;            // k-chunk 0 or 4 (plus +2 on 2nd iter... see below)
    // A: 128 rows x 32 floats = 1024 chunks of 16B; 256 thr x 4
    // B: 32 k x 256 n = 2048 chunks; 256 thr x 8

    auto issue = [&](int c) {
        const uint32_t aB = sb + (c % NSTAGE) * STAGE_STRIDE;
        const uint32_t bB = aB + A_STAGE_BYTES;
        const int k0 = c * KC;
        // A tile
#pragma unroll
        for (int i = 0; i < 4; i++) {
            int idx = tid + i * 256;
            int r   = idx >> 3;
            int c4  = (idx & 7) * 4;
            const float* src;
            if (PHASE == 1) src = Abase + (size_t)sTok[r] * KDIM + k0 + c4;
            else            src = Aexp + (size_t)min(m0 + r, cnt - 1) * KDIM + k0 + c4;
            cp16(aB + SWZ((uint32_t)(r * 128 + c4 * 4)), src);
        }
        // B tile
#pragma unroll
        for (int i = 0; i < 8; i++) {
            int idx = tid + i * 256;
            int k   = idx >> 6;            // 0..31
            int n   = (idx & 63) * 4;      // 0..252
            const float* src = Wexp + (size_t)(k0 + k) * NDIM + n0 + n;
            uint32_t dst = bB + (uint32_t)(k * (NT * 4) + ((n ^ ((k & 3) << 3)) * 4));
            cp16(dst, src);
        }
        CP_COMMIT();
    };

    float acc[4][8][4];
#pragma unroll
    for (int mi = 0; mi < 4; mi++)
#pragma unroll
        for (int ni = 0; ni < 8; ni++)
#pragma unroll
            for (int q = 0; q < 4; q++) acc[mi][ni][q] = 0.0f;

    issue(0);
    issue(1);

    for (int c = 0; c < NC; c++) {
        CP_WAIT1();
        __syncthreads();
        if (c + 2 < NC) issue(c + 2); else CP_COMMIT();

        const uint32_t aB = sb + (c % NSTAGE) * STAGE_STRIDE;
        const uint32_t bB = aB + A_STAGE_BYTES;
#pragma unroll
        for (int ks = 0; ks < 4; ks++) {
            const int kb = ks * 8;
            uint32_t b0[8], b1[8];
#pragma unroll
            for (int ni = 0; ni < 8; ni++) {
                int n = wn + ni * 8 + grp;
                uint32_t swn = (uint32_t)(n ^ (tig << 3)) * 4;
                uint32_t r0, r1;
                asm volatile("ld.shared.b32 %0, [%1];" : "=r"(r0)
                             : "r"(bB + (uint32_t)((kb + tig) * (NT * 4)) + swn));
                asm volatile("ld.shared.b32 %0, [%1];" : "=r"(r1)
                             : "r"(bB + (uint32_t)((kb + tig + 4) * (NT * 4)) + swn));
                b0[ni] = cvt_frag(r0);
                b1[ni] = cvt_frag(r1);
            }
#pragma unroll
            for (int mi = 0; mi < 4; mi++) {
                int m = wm + mi * 16;
                uint32_t a0, a1, a2, a3;
                asm volatile("ld.shared.b32 %0, [%1];" : "=r"(a0)
                             : "r"(aB + SWZ((uint32_t)((m + grp) * 128 + (kb + tig) * 4))));
                asm volatile("ld.shared.b32 %0, [%1];" : "=r"(a1)
                             : "r"(aB + SWZ((uint32_t)((m + grp + 8) * 128 + (kb + tig) * 4))));
                asm volatile("ld.shared.b32 %0, [%1];" : "=r"(a2)
                             : "r"(aB + SWZ((uint32_t)((m + grp) * 128 + (kb + tig + 4) * 4))));
                asm volatile("ld.shared.b32 %0, [%1];" : "=r"(a3)
                             : "r"(aB + SWZ((uint32_t)((m + grp + 8) * 128 + (kb + tig + 4) * 4))));
                a0 = cvt_frag(a0); a1 = cvt_frag(a1);
                a2 = cvt_frag(a2); a3 = cvt_frag(a3);
#pragma unroll
                for (int ni = 0; ni < 8; ni++)
                    mma_tf32(acc[mi][ni], a0, a1, a2, a3, b0[ni], b1[ni]);
            }
        }
    }
    asm volatile("cp.async.wait_group 0;" ::: "memory");

    // ------------------------------ epilogue ------------------------------
#pragma unroll
    for (int mi = 0; mi < 4; mi++) {
#pragma unroll
        for (int ni = 0; ni < 8; ni++) {
            int gn = n0 + wn + ni * 8 + tig * 2;
            float bv0 = bias[(size_t)e * NDIM + gn];
            float bv1 = bias[(size_t)e * NDIM + gn + 1];
#pragma unroll
            for (int half = 0; half < 2; half++) {
                int r = m0 + wm + mi * 16 + grp + half * 8;
                if (r < cnt) {
                    float v0 = acc[mi][ni][half * 2 + 0] + bv0;
                    float v1 = acc[mi][ni][half * 2 + 1] + bv1;
                    if (PHASE == 1) {
                        float* dst = g_h + (size_t)e * T_TOK * F_DIM + (size_t)r * F_DIM + gn;
                        dst[0] = to_tf32(gelu_exact(v0));   // pre-round for phase-2 A
                        dst[1] = to_tf32(gelu_exact(v1));
                    } else {
                        int   tok = sTok[r - m0];
                        float wt  = sWt[r - m0];
                        atomicAdd(&out[(size_t)tok * H_DIM + gn],     wt * v0);
                        atomicAdd(&out[(size_t)tok * H_DIM + gn + 1], wt * v1);
                    }
                }
            }
        }
    }
}

// ------------------------------ launch ------------------------------------
extern "C" void kernel_launch(void* const* d_in, const int* in_sizes, int n_in,
                              void* d_out, int out_size) {
    const float* x  = (const float*)d_in[0];
    const float* rw = (const float*)d_in[1];
    const float* rb = (const float*)d_in[2];
    const float* w1 = (const float*)d_in[3];
    const float* b1 = (const float*)d_in[4];
    const float* w2 = (const float*)d_in[5];
    const float* b2 = (const float*)d_in[6];
    float* out = (float*)d_out;

    cudaFuncSetAttribute(moe_gemm<H_DIM, F_DIM, 1>,
                         cudaFuncAttributeMaxDynamicSharedMemorySize, SMEM_BYTES);
    cudaFuncSetAttribute(moe_gemm<F_DIM, H_DIM, 2>,
                         cudaFuncAttributeMaxDynamicSharedMemorySize, SMEM_BYTES);

    zero_kernel<<<(T_TOK * H_DIM + 255) / 256, 256>>>(out);
    router_kernel<<<(T_TOK * 32 + 255) / 256, 256>>>(x, rw, rb);
    moe_gemm<H_DIM, F_DIM, 1>
        <<<dim3(T_TOK / 128, F_DIM / NT, N_EXP), 256, SMEM_BYTES>>>(x, w1, b1, nullptr);
    moe_gemm<F_DIM, H_DIM, 2>
        <<<dim3(T_TOK / 128, H_DIM / NT, N_EXP), 256, SMEM_BYTES>>>(nullptr, w2, b2, out);
}

// round 7
// speedup vs baseline: 3.1067x; 1.4967x over previous
#include <cuda_runtime.h>
#include <cuda_fp16.h>
#include <cstdint>

// Problem constants
#define T_TOK 4096
#define H_DIM 1024
#define F_DIM 4096
#define N_EXP 8

// Tiling: CTA 128m x 256n x 32k, 8 warps (2m x 4n), warp tile 64x64, fp16 MMA
#define NT 256
#define KC 32
#define NSTAGE 6
#define A_STAGE_BYTES (128 * 64)          // 128 rows x 32 halves (64B)
#define B_STAGE_BYTES (KC * NT * 2)       // 32 k-rows x 512B
#define STAGE_STRIDE  (A_STAGE_BYTES + B_STAGE_BYTES)   // 24KB
#define SMEM_TILES_OFF 1024
#define SMEM_BYTES (SMEM_TILES_OFF + NSTAGE * STAGE_STRIDE)

// -------- device scratch --------
__device__ int    g_cnt[N_EXP];
__device__ int    g_list[N_EXP][T_TOK];
__device__ float  g_wt[N_EXP][T_TOK];
__device__ __half g_xh[(size_t)T_TOK * H_DIM];
__device__ __half g_w1h[(size_t)N_EXP * H_DIM * F_DIM];
__device__ __half g_w2h[(size_t)N_EXP * F_DIM * H_DIM];
__device__ __half g_h[(size_t)N_EXP * T_TOK * F_DIM];

// -------- helpers --------
__device__ __forceinline__ uint32_t smem_u32(const void* p) {
    uint32_t a;
    asm("{ .reg .u64 t; cvta.to.shared.u64 t, %1; cvt.u32.u64 %0, t; }" : "=r"(a) : "l"(p));
    return a;
}
__device__ __forceinline__ void cp16(uint32_t dst, const void* src) {
    asm volatile("cp.async.cg.shared.global [%0], [%1], 16;" :: "r"(dst), "l"(src) : "memory");
}
#define CP_COMMIT() asm volatile("cp.async.commit_group;" ::: "memory")

__device__ __forceinline__ void mma_f16(float c[4], const uint32_t a[4],
                                        uint32_t b0, uint32_t b1) {
    asm volatile(
        "mma.sync.aligned.m16n8k16.row.col.f32.f16.f16.f32 "
        "{%0,%1,%2,%3}, {%4,%5,%6,%7}, {%8,%9}, {%0,%1,%2,%3};"
        : "+f"(c[0]), "+f"(c[1]), "+f"(c[2]), "+f"(c[3])
        : "r"(a[0]), "r"(a[1]), "r"(a[2]), "r"(a[3]), "r"(b0), "r"(b1));
}
#define LDM_X4(r0, r1, r2, r3, addr) \
    asm volatile("ldmatrix.sync.aligned.m8n8.x4.shared.b16 {%0,%1,%2,%3}, [%4];" \
                 : "=r"(r0), "=r"(r1), "=r"(r2), "=r"(r3) : "r"(addr))
#define LDM_X4T(r0, r1, r2, r3, addr) \
    asm volatile("ldmatrix.sync.aligned.m8n8.x4.trans.shared.b16 {%0,%1,%2,%3}, [%4];" \
                 : "=r"(r0), "=r"(r1), "=r"(r2), "=r"(r3) : "r"(addr))

__device__ __forceinline__ float gelu_exact(float x) {
    return 0.5f * x * (1.0f + erff(x * 0.70710678118654752f));
}

// ------------------------------ convert kernel -----------------------------
__global__ void cvt_kernel(const float4* __restrict__ src, __half2* __restrict__ dst,
                           int n4) {
    int i = blockIdx.x * blockDim.x + threadIdx.x;
    if (i < n4) {
        float4 v = src[i];
        dst[2 * i]     = __floats2half2_rn(v.x, v.y);
        dst[2 * i + 1] = __floats2half2_rn(v.z, v.w);
    }
}

// ------------------------------ zero kernel --------------------------------
__global__ void zero_kernel(float* __restrict__ out) {
    int i = blockIdx.x * blockDim.x + threadIdx.x;
    if (i < T_TOK * H_DIM) out[i] = 0.0f;
    if (i < N_EXP) g_cnt[i] = 0;
}

// ------------------------------ router kernel ------------------------------
__global__ void router_kernel(const float* __restrict__ x,
                              const float* __restrict__ rw,
                              const float* __restrict__ rb) {
    int gwarp = (blockIdx.x * blockDim.x + threadIdx.x) >> 5;
    if (gwarp >= T_TOK) return;
    int lane = threadIdx.x & 31;
    const float* xr = x + (size_t)gwarp * H_DIM;
    float p[N_EXP];
#pragma unroll
    for (int e = 0; e < N_EXP; e++) p[e] = 0.0f;
    for (int i = lane; i < H_DIM; i += 32) {
        float xv = xr[i];
        const float4* r4 = (const float4*)(rw + i * N_EXP);
        float4 ra = r4[0], rc = r4[1];
        p[0] += xv * ra.x; p[1] += xv * ra.y; p[2] += xv * ra.z; p[3] += xv * ra.w;
        p[4] += xv * rc.x; p[5] += xv * rc.y; p[6] += xv * rc.z; p[7] += xv * rc.w;
    }
#pragma unroll
    for (int e = 0; e < N_EXP; e++) {
#pragma unroll
        for (int o = 16; o > 0; o >>= 1) p[e] += __shfl_xor_sync(0xffffffffu, p[e], o);
    }
    if (lane == 0) {
#pragma unroll
        for (int e = 0; e < N_EXP; e++) p[e] += rb[e];
        int i1 = 0;
#pragma unroll
        for (int e = 1; e < N_EXP; e++) if (p[e] > p[i1]) i1 = e;
        int i2 = (i1 == 0) ? 1 : 0;
#pragma unroll
        for (int e = 0; e < N_EXP; e++) if (e != i1 && p[e] > p[i2]) i2 = e;
        float wa = 1.0f / (1.0f + expf(p[i2] - p[i1]));
        float wb = 1.0f - wa;
        int p1 = atomicAdd(&g_cnt[i1], 1);
        g_list[i1][p1] = gwarp; g_wt[i1][p1] = wa;
        int p2 = atomicAdd(&g_cnt[i2], 1);
        g_list[i2][p2] = gwarp; g_wt[i2][p2] = wb;
    }
}

// --------------------------- grouped GEMM kernel ---------------------------
// A smem: [m(128)][k(32)] fp16, 64B rows, unit swizzle u^=(row&3).
// B smem: [k(32)][n(256)] fp16, 512B rows, unit swizzle u^=(k&7).
template <int KDIM, int NDIM, int PHASE>
__global__ void __launch_bounds__(256)
moe_gemm(const __half* __restrict__ Ah,
         const __half* __restrict__ Wh,
         const float* __restrict__ bias,
         float* __restrict__ out) {
    extern __shared__ char smem[];
    const int e   = blockIdx.z;
    const int cnt = g_cnt[e];
    const int m0  = blockIdx.x * 128;
    if (m0 >= cnt) return;
    const int n0  = blockIdx.y * NT;

    const int tid  = threadIdx.x;
    const int lane = tid & 31;
    const int warp = tid >> 5;
    const int wm   = (warp & 1) * 64;
    const int wn   = (warp >> 1) * 64;
    const int grp  = lane >> 2;
    const int tig  = lane & 3;

    int*   sTok = (int*)(smem);          // [128]
    float* sWt  = (float*)(smem + 512);  // [128]

    if (tid < 128) {
        int mc = min(m0 + tid, cnt - 1);
        sTok[tid] = g_list[e][mc];
        sWt[tid]  = g_wt[e][mc];
    }
    __syncthreads();

    const __half* Aexp = (PHASE == 1) ? Ah : (g_h + (size_t)e * T_TOK * F_DIM);
    const __half* Wexp = Wh + (size_t)e * KDIM * NDIM;
    constexpr int NC = KDIM / KC;
    const uint32_t sb = smem_u32(smem) + SMEM_TILES_OFF;

    auto issue = [&](int c) {
        const uint32_t aB = sb + (c % NSTAGE) * STAGE_STRIDE;
        const uint32_t bB = aB + A_STAGE_BYTES;
        const int k0 = c * KC;
        // A tile: 512 16B-chunks, 2 per thread
#pragma unroll
        for (int i = 0; i < 2; i++) {
            int idx = tid + i * 256;
            int r   = idx >> 2;
            int u   = idx & 3;
            const __half* src;
            if (PHASE == 1) src = Ah + (size_t)sTok[r] * KDIM + k0 + u * 8;
            else            src = Aexp + (size_t)min(m0 + r, cnt - 1) * KDIM + k0 + u * 8;
            cp16(aB + (uint32_t)(r * 64 + ((u ^ (r & 3)) << 4)), src);
        }
        // B tile: 1024 16B-chunks, 4 per thread
#pragma unroll
        for (int i = 0; i < 4; i++) {
            int idx = tid + i * 256;
            int k   = idx >> 5;
            int u   = idx & 31;
            const __half* src = Wexp + (size_t)(k0 + k) * NDIM + n0 + u * 8;
            cp16(bB + (uint32_t)(k * 512 + ((u ^ (k & 7)) << 4)), src);
        }
        CP_COMMIT();
    };

    float acc[4][8][4];
#pragma unroll
    for (int mi = 0; mi < 4; mi++)
#pragma unroll
        for (int ni = 0; ni < 8; ni++)
#pragma unroll
            for (int q = 0; q < 4; q++) acc[mi][ni][q] = 0.0f;

    // per-lane ldmatrix coordinates
    const int l7 = lane & 7;
    const int lh = (lane >> 3) & 1;
    const int lu = lane >> 4;            // 0/1: k-unit (A) or n-block (B)
    int aRow[4], aRx[4];
#pragma unroll
    for (int mi = 0; mi < 4; mi++) {
        int row = wm + mi * 16 + l7 + lh * 8;
        aRow[mi] = row * 64;
        aRx[mi]  = row & 3;
    }
    const int bUbase = (wn >> 3) + lu;

    // pipeline: prefetch depth NSTAGE-2; compute c = cc - (NSTAGE-2) for c in [0, NC)
#pragma unroll 1
    for (int cc = 0; cc < NC + NSTAGE - 2; cc++) {
        if (cc < NC) { issue(cc); } else { CP_COMMIT(); }
        if (cc < NSTAGE - 2) continue;
        const int c = cc - (NSTAGE - 2);
        asm volatile("cp.async.wait_group %0;" :: "n"(NSTAGE - 2) : "memory");
        __syncthreads();

        const uint32_t aB = sb + (c % NSTAGE) * STAGE_STRIDE;
        const uint32_t bB = aB + A_STAGE_BYTES;
#pragma unroll
        for (int ks = 0; ks < 2; ks++) {
            const int kl = ks * 16 + l7 + lh * 8;   // B k-row for this lane
            const uint32_t bkBase = bB + (uint32_t)(kl * 512);
            const int kx = kl & 7;
            uint32_t b0[8], b1[8];
#pragma unroll
            for (int pr = 0; pr < 4; pr++) {
                uint32_t addr = bkBase + (uint32_t)(((bUbase + pr * 2) ^ kx) << 4);
                LDM_X4T(b0[pr * 2], b1[pr * 2], b0[pr * 2 + 1], b1[pr * 2 + 1], addr);
            }
            uint32_t a[4][4];
#pragma unroll
            for (int mi = 0; mi < 4; mi++) {
                uint32_t addr = aB + (uint32_t)(aRow[mi] + (((ks * 2 + lu) ^ aRx[mi]) << 4));
                LDM_X4(a[mi][0], a[mi][1], a[mi][2], a[mi][3], addr);
            }
#pragma unroll
            for (int mi = 0; mi < 4; mi++)
#pragma unroll
                for (int ni = 0; ni < 8; ni++)
                    mma_f16(acc[mi][ni], a[mi], b0[ni], b1[ni]);
        }
    }
    asm volatile("cp.async.wait_group 0;" ::: "memory");

    // ------------------------------ epilogue ------------------------------
#pragma unroll
    for (int mi = 0; mi < 4; mi++) {
#pragma unroll
        for (int ni = 0; ni < 8; ni++) {
            int gn = n0 + wn + ni * 8 + tig * 2;
            float bv0 = bias[(size_t)e * NDIM + gn];
            float bv1 = bias[(size_t)e * NDIM + gn + 1];
#pragma unroll
            for (int half = 0; half < 2; half++) {
                int r = m0 + wm + mi * 16 + grp + half * 8;
                if (r < cnt) {
                    float v0 = acc[mi][ni][half * 2 + 0] + bv0;
                    float v1 = acc[mi][ni][half * 2 + 1] + bv1;
                    if (PHASE == 1) {
                        __half2* dst = (__half2*)(g_h + (size_t)e * T_TOK * F_DIM +
                                                  (size_t)r * F_DIM + gn);
                        *dst = __floats2half2_rn(gelu_exact(v0), gelu_exact(v1));
                    } else {
                        int   tok = sTok[r - m0];
                        float wt  = sWt[r - m0];
                        atomicAdd(&out[(size_t)tok * H_DIM + gn],     wt * v0);
                        atomicAdd(&out[(size_t)tok * H_DIM + gn + 1], wt * v1);
                    }
                }
            }
        }
    }
}

// ------------------------------ launch ------------------------------------
extern "C" void kernel_launch(void* const* d_in, const int* in_sizes, int n_in,
                              void* d_out, int out_size) {
    const float* x  = (const float*)d_in[0];
    const float* rw = (const float*)d_in[1];
    const float* rb = (const float*)d_in[2];
    const float* w1 = (const float*)d_in[3];
    const float* b1 = (const float*)d_in[4];
    const float* w2 = (const float*)d_in[5];
    const float* b2 = (const float*)d_in[6];
    float* out = (float*)d_out;

    cudaFuncSetAttribute(moe_gemm<H_DIM, F_DIM, 1>,
                         cudaFuncAttributeMaxDynamicSharedMemorySize, SMEM_BYTES);
    cudaFuncSetAttribute(moe_gemm<F_DIM, H_DIM, 2>,
                         cudaFuncAttributeMaxDynamicSharedMemorySize, SMEM_BYTES);

    __half *p_xh, *p_w1h, *p_w2h;
    cudaGetSymbolAddress((void**)&p_xh,  g_xh);
    cudaGetSymbolAddress((void**)&p_w1h, g_w1h);
    cudaGetSymbolAddress((void**)&p_w2h, g_w2h);

    const int n4_x  = T_TOK * H_DIM / 4;
    const int n4_w1 = N_EXP * H_DIM * F_DIM / 4;
    const int n4_w2 = N_EXP * F_DIM * H_DIM / 4;

    zero_kernel<<<(T_TOK * H_DIM + 255) / 256, 256>>>(out);
    cvt_kernel<<<(n4_x + 255) / 256, 256>>>((const float4*)x, (__half2*)p_xh, n4_x);
    cvt_kernel<<<(n4_w1 + 255) / 256, 256>>>((const float4*)w1, (__half2*)p_w1h, n4_w1);
    cvt_kernel<<<(n4_w2 + 255) / 256, 256>>>((const float4*)w2, (__half2*)p_w2h, n4_w2);
    router_kernel<<<(T_TOK * 32 + 255) / 256, 256>>>(x, rw, rb);
    moe_gemm<H_DIM, F_DIM, 1>
        <<<dim3(T_TOK / 128, F_DIM / NT, N_EXP), 256, SMEM_BYTES>>>(p_xh, p_w1h, b1, nullptr);
    moe_gemm<F_DIM, H_DIM, 2>
        <<<dim3(T_TOK / 128, H_DIM / NT, N_EXP), 256, SMEM_BYTES>>>(nullptr, p_w2h, b2, out);
}